// round 10
// baseline (speedup 1.0000x reference)
#include <cuda_runtime.h>
#include <cuda_fp16.h>
#include <cstdint>

#define N_NODES 100000
#define HF 64
#define E_MAX 1600000
#define SCAN_T 512
#define NBLK_SCAN 196            // ceil(100000/512)
#define GEMM_BLOCKS 782          // ceil(100000/128)
#define FILL_BLOCKS 1024

// ---------------- scratch (static device globals; no allocation) -------------
__device__ __align__(16) __half g_hs[N_NODES * HF];  // UNSCALED X@W, fp16
__device__ __align__(16) __half g_x[N_NODES * HF];   // layer activations, fp16
__device__ float g_dinv[N_NODES];
__device__ int   g_cnt[N_NODES];
__device__ int   g_off[N_NODES];      // block-local exclusive prefix (512-blocks)
__device__ int   g_cur[N_NODES];
__device__ int   g_bsum_raw[256];
__device__ int   g_bsum[256];         // final per-512-block base offsets
__device__ int2  g_csre[E_MAX];       // {src, bits(dinv[src])} sorted by dst
__device__ int   g_ticket;
__device__ int   g_is_i32 = 0;

// ---------------- prep -------------------------------------------------------
__global__ void k_init(const int* __restrict__ ei32, int nwords) {
    int i = blockIdx.x * SCAN_T + threadIdx.x;
    if (i < N_NODES) g_cnt[i] = 0;
    int w = 2 * i + 1;   // int64 high words are 0; int32 data isn't
    if (i < 2048 && w < nwords) {
        if (ei32[w] != 0) atomicOr(&g_is_i32, 1);
    }
}

__global__ void k_prep(const void* __restrict__ eiv, int E) {
    if (blockIdx.x == 0 && threadIdx.x == 0) g_ticket = 0;
    const bool i32 = (g_is_i32 != 0);
    const int* __restrict__ p32 = (const int*)eiv;
    const long long* __restrict__ p64 = (const long long*)eiv;
    int stride = gridDim.x * blockDim.x;
    for (int i = blockIdx.x * blockDim.x + threadIdx.x; i < E; i += stride) {
        int d = i32 ? p32[E + i] : (int)p64[(size_t)E + i];
        if ((unsigned)d >= N_NODES) d = 0;
        atomicAdd(&g_cnt[d], 1);
    }
}

// scan1: block-local exclusive scan + dinv + cur-zero; LAST block scans the
// 196 block sums into g_bsum (deterministic last-block pattern).
__global__ __launch_bounds__(SCAN_T) void k_scan1() {
    __shared__ int sh[SCAN_T];
    __shared__ int sh_last;
    int t = threadIdx.x;
    int i = blockIdx.x * SCAN_T + t;
    int c = (i < N_NODES) ? g_cnt[i] : 0;
    sh[t] = c;
    __syncthreads();
    int v = c;
#pragma unroll
    for (int ofs = 1; ofs < SCAN_T; ofs <<= 1) {
        int x = (t >= ofs) ? sh[t - ofs] : 0;
        __syncthreads();
        v += x;
        sh[t] = v;
        __syncthreads();
    }
    if (i < N_NODES) {
        g_off[i] = v - c;
        g_cur[i] = 0;
        g_dinv[i] = rsqrtf((float)c + 1.0f);
    }
    if (t == SCAN_T - 1) {
        g_bsum_raw[blockIdx.x] = v;
        __threadfence();
        int tk = atomicAdd(&g_ticket, 1);
        sh_last = (tk == gridDim.x - 1);
    }
    __syncthreads();
    if (sh_last) {
        int c2 = (t < NBLK_SCAN) ? g_bsum_raw[t] : 0;
        sh[t] = c2;
        __syncthreads();
        int v2 = c2;
#pragma unroll
        for (int ofs = 1; ofs < 256; ofs <<= 1) {
            int x = (t >= ofs) ? sh[t - ofs] : 0;
            __syncthreads();
            v2 += x;
            sh[t] = v2;
            __syncthreads();
        }
        if (t < NBLK_SCAN) g_bsum[t] = v2 - c2;
    }
}

// ---------------- tensor-core GEMM body (shared) ------------------------------
#define MMA16816(d0,d1,d2,d3,a0,a1,a2,a3,b0,b1)                          \
    asm volatile("mma.sync.aligned.m16n8k16.row.col.f32.f16.f16.f32 "   \
                 "{%0,%1,%2,%3},{%4,%5,%6,%7},{%8,%9},{%0,%1,%2,%3};"   \
                 : "+f"(d0), "+f"(d1), "+f"(d2), "+f"(d3)               \
                 : "r"(a0), "r"(a1), "r"(a2), "r"(a3), "r"(b0), "r"(b1))

// C[M,64] = X[M,K] @ W[K,64]; HEAD=0: g_hs=half(C) (unscaled);
// HEAD=1: out[f*N+m]=sigmoid(C+bias[f]) transposed.
template <int K, bool XHALF, bool HEAD>
__device__ __forceinline__
void mma_body(int m0, const float* __restrict__ Xf, const float* __restrict__ W,
              const float* __restrict__ bias, float* __restrict__ out)
{
    constexpr int BM = 128, BK = 64;
    constexpr int XSTR = 72;
    constexpr int WSTR = 136;
    __shared__ __align__(16) char sraw[BM * XSTR * 2 + 64 * WSTR * 2];
    __half* Xs = (__half*)sraw;                       // [128][72]
    __half* Wt = (__half*)(sraw + BM * XSTR * 2);     // [64][136]
    float*  stg = (float*)sraw;                       // head staging [128][68]

    const int tid  = threadIdx.x;
    const int w    = tid >> 5;
    const int lane = tid & 31;
    const int r    = lane >> 2;
    const int q    = lane & 3;

    for (int idx = tid; idx < K * 64; idx += 256) {
        int k = idx >> 6, n = idx & 63;
        Wt[n * WSTR + k] = __float2half(W[idx]);
    }

    float acc[8][4];
#pragma unroll
    for (int j = 0; j < 8; j++)
        acc[j][0] = acc[j][1] = acc[j][2] = acc[j][3] = 0.f;

    for (int k0 = 0; k0 < K; k0 += BK) {
        if (XHALF) {
            for (int idx = tid; idx < BM * 8; idx += 256) {
                int m = idx >> 3, c = idx & 7;
                int gm = m0 + m;
                uint4 v = make_uint4(0, 0, 0, 0);
                if (gm < N_NODES)
                    v = *(const uint4*)((const __half*)g_x + (size_t)gm * 64 + 8 * c);
                *(uint4*)(Xs + m * XSTR + 8 * c) = v;
            }
        } else {
            for (int idx = tid; idx < BM * 32; idx += 256) {
                int m = idx >> 5, c = idx & 31;
                int gm = m0 + m;
                __half2 h = __floats2half2_rn(0.f, 0.f);
                if (gm < N_NODES) {
                    float2 v = *(const float2*)(Xf + (size_t)gm * K + k0 + 2 * c);
                    h = __floats2half2_rn(v.x, v.y);
                }
                *(__half2*)(Xs + m * XSTR + 2 * c) = h;
            }
        }
        __syncthreads();
#pragma unroll
        for (int kc = 0; kc < BK; kc += 16) {
            unsigned a0, a1, a2, a3;
            const __half* Ab = Xs + (16 * w + r) * XSTR + kc + 2 * q;
            a0 = *(const unsigned*)(Ab);
            a1 = *(const unsigned*)(Ab + 8 * XSTR);
            a2 = *(const unsigned*)(Ab + 8);
            a3 = *(const unsigned*)(Ab + 8 * XSTR + 8);
#pragma unroll
            for (int j = 0; j < 8; j++) {
                const __half* Bb = Wt + (8 * j + r) * WSTR + (k0 + kc) + 2 * q;
                unsigned b0 = *(const unsigned*)(Bb);
                unsigned b1 = *(const unsigned*)(Bb + 8);
                MMA16816(acc[j][0], acc[j][1], acc[j][2], acc[j][3],
                         a0, a1, a2, a3, b0, b1);
            }
        }
        __syncthreads();
    }

    if (!HEAD) {
        int row0 = m0 + 16 * w + r;
        int row1 = row0 + 8;
        if (row0 < N_NODES) {
#pragma unroll
            for (int j = 0; j < 8; j++)
                *(__half2*)(g_hs + (size_t)row0 * 64 + 8 * j + 2 * q) =
                    __floats2half2_rn(acc[j][0], acc[j][1]);
        }
        if (row1 < N_NODES) {
#pragma unroll
            for (int j = 0; j < 8; j++)
                *(__half2*)(g_hs + (size_t)row1 * 64 + 8 * j + 2 * q) =
                    __floats2half2_rn(acc[j][2], acc[j][3]);
        }
    } else {
        constexpr int SS = 68;
        int rl0 = 16 * w + r;
        int rl1 = rl0 + 8;
#pragma unroll
        for (int j = 0; j < 8; j++) {
            int col = 8 * j + 2 * q;
            float bx = bias[col], by = bias[col + 1];
            stg[rl0 * SS + col]     = 1.f / (1.f + __expf(-(acc[j][0] + bx)));
            stg[rl0 * SS + col + 1] = 1.f / (1.f + __expf(-(acc[j][1] + by)));
            stg[rl1 * SS + col]     = 1.f / (1.f + __expf(-(acc[j][2] + bx)));
            stg[rl1 * SS + col + 1] = 1.f / (1.f + __expf(-(acc[j][3] + by)));
        }
        __syncthreads();
        for (int idx = tid; idx < BM * 64; idx += 256) {
            int f = idx >> 7;
            int ml = idx & 127;
            int m = m0 + ml;
            if (m < N_NODES)
                out[(size_t)f * N_NODES + m] = stg[ml * SS + f];
        }
    }
}

// ---------------- fused: GEMM1 (blocks 0..781) || CSR fill (rest) -------------
__global__ __launch_bounds__(256)
void k_fill_mma1(const void* __restrict__ eiv, int E,
                 const float* __restrict__ Xf, const float* __restrict__ W)
{
    if (blockIdx.x < GEMM_BLOCKS) {
        mma_body<128, false, false>(blockIdx.x * 128, Xf, W, nullptr, nullptr);
        return;
    }
    // fill role
    const int fb = blockIdx.x - GEMM_BLOCKS;
    const bool i32 = (g_is_i32 != 0);
    const int* __restrict__ p32 = (const int*)eiv;
    const long long* __restrict__ p64 = (const long long*)eiv;
    int stride = FILL_BLOCKS * 256;
    for (int e = fb * 256 + threadIdx.x; e < E; e += stride) {
        int s, d;
        if (i32) { s = p32[e]; d = p32[E + e]; }
        else     { s = (int)p64[e]; d = (int)p64[(size_t)E + e]; }
        if ((unsigned)s >= N_NODES) s = 0;
        if ((unsigned)d >= N_NODES) d = 0;
        int pos = g_off[d] + g_bsum[d >> 9] + atomicAdd(&g_cur[d], 1);
        g_csre[pos] = make_int2(s, __float_as_int(g_dinv[s]));
    }
}

// plain GEMM kernels (layer2 + head)
template <int K, bool XHALF, bool HEAD>
__global__ __launch_bounds__(256)
void k_mma(const float* __restrict__ Xf, const float* __restrict__ W,
           const float* __restrict__ bias, float* __restrict__ out)
{
    mma_body<K, XHALF, HEAD>(blockIdx.x * 128, Xf, W, bias, out);
}

// ---------------- gather: g_x = relu(dinv_g*(Σ dinv_s*h_s + dinv_g*h_g) + b) --
__global__ __launch_bounds__(256)
void k_gather(const float* __restrict__ bias)
{
    int g = (blockIdx.x * 256 + threadIdx.x) >> 4;
    int l = threadIdx.x & 15;
    if (g >= N_NODES) return;

    const int beg = g_off[g] + g_bsum[g >> 9];
    const int deg = g_cnt[g];
    const int end = beg + deg;
    const float dg = g_dinv[g];

    float4 acc;
    {
        uint2 u = *(const uint2*)(g_hs + (size_t)g * HF + 4 * l);
        float2 p0 = __half22float2(*(__half2*)&u.x);
        float2 p1 = __half22float2(*(__half2*)&u.y);
        acc = make_float4(dg * p0.x, dg * p0.y, dg * p1.x, dg * p1.y);
    }

    int j = beg;
    for (; j + 2 <= end; j += 2) {
        int2 e0 = g_csre[j];
        int2 e1 = g_csre[j + 1];
        uint2 u0 = *(const uint2*)(g_hs + (size_t)e0.x * HF + 4 * l);
        uint2 u1 = *(const uint2*)(g_hs + (size_t)e1.x * HF + 4 * l);
        float d0 = __int_as_float(e0.y);
        float d1 = __int_as_float(e1.y);
        float2 a0 = __half22float2(*(__half2*)&u0.x);
        float2 a1 = __half22float2(*(__half2*)&u0.y);
        float2 c0 = __half22float2(*(__half2*)&u1.x);
        float2 c1 = __half22float2(*(__half2*)&u1.y);
        acc.x = fmaf(d0, a0.x, fmaf(d1, c0.x, acc.x));
        acc.y = fmaf(d0, a0.y, fmaf(d1, c0.y, acc.y));
        acc.z = fmaf(d0, a1.x, fmaf(d1, c1.x, acc.z));
        acc.w = fmaf(d0, a1.y, fmaf(d1, c1.y, acc.w));
    }
    if (j < end) {
        int2 e0 = g_csre[j];
        uint2 u0 = *(const uint2*)(g_hs + (size_t)e0.x * HF + 4 * l);
        float d0 = __int_as_float(e0.y);
        float2 a0 = __half22float2(*(__half2*)&u0.x);
        float2 a1 = __half22float2(*(__half2*)&u0.y);
        acc.x = fmaf(d0, a0.x, acc.x);
        acc.y = fmaf(d0, a0.y, acc.y);
        acc.z = fmaf(d0, a1.x, acc.z);
        acc.w = fmaf(d0, a1.y, acc.w);
    }

    float4 b = *(const float4*)(bias + 4 * l);
    float ox = fmaxf(fmaf(dg, acc.x, b.x), 0.f);
    float oy = fmaxf(fmaf(dg, acc.y, b.y), 0.f);
    float oz = fmaxf(fmaf(dg, acc.z, b.z), 0.f);
    float ow = fmaxf(fmaf(dg, acc.w, b.w), 0.f);
    __half2 h0 = __floats2half2_rn(ox, oy);
    __half2 h1 = __floats2half2_rn(oz, ow);
    uint2 u;
    u.x = *(unsigned*)&h0;
    u.y = *(unsigned*)&h1;
    *(uint2*)(g_x + (size_t)g * HF + 4 * l) = u;
}

// ---------------- launch ------------------------------------------------------
extern "C" void kernel_launch(void* const* d_in, const int* in_sizes, int n_in,
                              void* d_out, int out_size)
{
    const float* x  = (const float*)d_in[0];
    const void*  ei = d_in[1];
    const float* W1 = (const float*)d_in[2];
    const float* b1 = (const float*)d_in[3];
    const float* W2 = (const float*)d_in[4];
    const float* b2 = (const float*)d_in[5];
    const float* Wl = (const float*)d_in[6];
    const float* bl = (const float*)d_in[7];
    float*       out = (float*)d_out;
    const int nwords = in_sizes[1];
    const int E = nwords / 2;

    const int gather_blocks = (N_NODES * 16 + 255) / 256; // 6250

    k_init<<<NBLK_SCAN, SCAN_T>>>((const int*)ei, nwords);
    k_prep<<<2048, 256>>>(ei, E);
    k_scan1<<<NBLK_SCAN, SCAN_T>>>();
    k_fill_mma1<<<GEMM_BLOCKS + FILL_BLOCKS, 256>>>(ei, E, x, W1);

    k_gather<<<gather_blocks, 256>>>(b1);
    k_mma<64, true, false><<<GEMM_BLOCKS, 256>>>(nullptr, W2, nullptr, nullptr);
    k_gather<<<gather_blocks, 256>>>(b2);
    k_mma<64, true, true><<<GEMM_BLOCKS, 256>>>(nullptr, Wl, bl, out);

    (void)n_in; (void)out_size;
}